// round 12
// baseline (speedup 1.0000x reference)
#include <cuda_runtime.h>
#include <math_constants.h>

#define NPTS 4096
#define DDATA 1024
#define DLAT 64
#define NEDGE (NPTS - 1)
#define ROUNDS 12

// ---- scratch (no allocations allowed: device globals) ----
static __device__ float g_ddist[(size_t)NPTS * NPTS];   // raw data distances fp32
static __device__ float g_ldist[(size_t)NPTS * NPTS];   // raw latent distances fp32
static __device__ float g_sqd[NPTS];
static __device__ float g_sql[NPTS];
static __device__ float g_ae[NPTS];
static __device__ int   g_edges[2][NEDGE * 2];
static __device__ int   g_ecnt[2];
static __device__ int   g_done[2];
static __device__ int   g_comp[2][NPTS];
static __device__ int   g_parent[2][NPTS];
static __device__ unsigned long long g_nbest[2][NPTS];
static __device__ unsigned g_dmax_bits;
static __device__ float g_topo;

__global__ void init_kernel() {
    int i = blockIdx.x * blockDim.x + threadIdx.x;
    if (i < NPTS) {
        g_comp[0][i] = i; g_comp[1][i] = i;
        // self-pointing sentinel: target inside own component -> forces round-0 scan
        g_nbest[0][i] = ((unsigned long long)i << 12) | (unsigned long long)i;
        g_nbest[1][i] = ((unsigned long long)i << 12) | (unsigned long long)i;
    }
    if (i == 0) {
        g_dmax_bits = 0u;
        g_ecnt[0] = 0; g_ecnt[1] = 0;
        g_done[0] = 0; g_done[1] = 0;
    }
}

// ---- AE loss + squared norms of y_true (one block per row) ----
__global__ void __launch_bounds__(256) ae_sq_kernel(
    const float* __restrict__ yt, const float* __restrict__ yp) {
    int row = blockIdx.x, tid = threadIdx.x;
    float4 a = ((const float4*)(yt + (size_t)row * DDATA))[tid];
    float4 b = ((const float4*)(yp + (size_t)row * DDATA))[tid];
    float dx = a.x - b.x, dy = a.y - b.y, dz = a.z - b.z, dw = a.w - b.w;
    float ae = dx * dx + dy * dy + dz * dz + dw * dw;
    float sq = a.x * a.x + a.y * a.y + a.z * a.z + a.w * a.w;
#pragma unroll
    for (int off = 16; off; off >>= 1) {
        ae += __shfl_down_sync(0xffffffffu, ae, off);
        sq += __shfl_down_sync(0xffffffffu, sq, off);
    }
    __shared__ float sae[8], ssq[8];
    if ((tid & 31) == 0) { sae[tid >> 5] = ae; ssq[tid >> 5] = sq; }
    __syncthreads();
    if (tid < 8) {
        ae = sae[tid]; sq = ssq[tid];
#pragma unroll
        for (int off = 4; off; off >>= 1) {
            ae += __shfl_down_sync(0xffu, ae, off);
            sq += __shfl_down_sync(0xffu, sq, off);
        }
        if (tid == 0) { g_ae[row] = ae * (1.0f / DDATA); g_sqd[row] = sq; }
    }
}

// ---- squared norms of latent rows (one warp per row) ----
__global__ void __launch_bounds__(32) sq_lat_kernel(const float* __restrict__ lat) {
    int row = blockIdx.x, tid = threadIdx.x;
    float2 v = ((const float2*)(lat + (size_t)row * DLAT))[tid];
    float s = v.x * v.x + v.y * v.y;
#pragma unroll
    for (int off = 16; off; off >>= 1) s += __shfl_down_sync(0xffffffffu, s, off);
    if (tid == 0) g_sql[row] = s;
}

// ---- fused gram -> Euclidean distance matrices (fp32 out) ----
// grid (33, 32): bx<32 & by<=bx -> data tile (by,bx); bx<32 & by>bx -> latent
// tile (bx,by); bx==32 -> latent diagonal tile (by,by). 128x128 tile, 256 thr,
// 8x8 per thread, BK=8. (Proven R2/R7 mainloop + numerics.)
__global__ void __launch_bounds__(256) gram_kernel(
    const float* __restrict__ Yd, const float* __restrict__ Yl) {
    int bx = blockIdx.x, by = blockIdx.y;
    int bi, bj, which;
    if (bx < 32) {
        if (by <= bx) { which = 0; bi = by; bj = bx; }
        else          { which = 1; bi = bx; bj = by; }
    } else            { which = 1; bi = by; bj = by; }
    const float* __restrict__ X  = which ? Yl : Yd;
    const int K = which ? DLAT : DDATA;
    const float* __restrict__ sq = which ? g_sql : g_sqd;
    float* __restrict__ D = which ? g_ldist : g_ddist;

    __shared__ float As[8][128], Bs[8][128];
    int tid = threadIdx.x;
    int tx = tid & 15, ty = tid >> 4;

    float acc[8][8];
#pragma unroll
    for (int m = 0; m < 8; m++)
#pragma unroll
        for (int n = 0; n < 8; n++) acc[m][n] = 0.f;

    int lr = tid >> 1;
    int lk = (tid & 1) << 2;
    const float* Ap = X + (size_t)(bi * 128 + lr) * K + lk;
    const float* Bp = X + (size_t)(bj * 128 + lr) * K + lk;

    for (int k0 = 0; k0 < K; k0 += 8) {
        float4 a = *(const float4*)(Ap + k0);
        float4 b = *(const float4*)(Bp + k0);
        __syncthreads();
        As[lk + 0][lr] = a.x; As[lk + 1][lr] = a.y;
        As[lk + 2][lr] = a.z; As[lk + 3][lr] = a.w;
        Bs[lk + 0][lr] = b.x; Bs[lk + 1][lr] = b.y;
        Bs[lk + 2][lr] = b.z; Bs[lk + 3][lr] = b.w;
        __syncthreads();
#pragma unroll
        for (int kk = 0; kk < 8; kk++) {
            float ar[8], br[8];
            *(float4*)(ar)     = *(const float4*)(&As[kk][ty * 8]);
            *(float4*)(ar + 4) = *(const float4*)(&As[kk][ty * 8 + 4]);
            *(float4*)(br)     = *(const float4*)(&Bs[kk][tx * 8]);
            *(float4*)(br + 4) = *(const float4*)(&Bs[kk][tx * 8 + 4]);
#pragma unroll
            for (int m = 0; m < 8; m++)
#pragma unroll
                for (int n = 0; n < 8; n++) acc[m][n] += ar[m] * br[n];
        }
    }

    // epilogue: d = sqrt(max(sq_i + sq_j - 2g, 0)); write fp32 both halves
    float sqa[8], sqb[8];
#pragma unroll
    for (int m = 0; m < 8; m++) sqa[m] = sq[bi * 128 + ty * 8 + m];
#pragma unroll
    for (int n = 0; n < 8; n++) sqb[n] = sq[bj * 128 + tx * 8 + n];

    float dmat[8][8];
    float lmax = 0.f;
#pragma unroll
    for (int m = 0; m < 8; m++)
#pragma unroll
        for (int n = 0; n < 8; n++) {
            float d2 = sqa[m] + sqb[n] - 2.0f * acc[m][n];
            float d = (d2 > 0.f) ? sqrtf(d2) : 0.f;
            dmat[m][n] = d;
            lmax = fmaxf(lmax, d);
        }

#pragma unroll
    for (int m = 0; m < 8; m++) {
        int gi = bi * 128 + ty * 8 + m;
        float* dst = D + (size_t)gi * NPTS + bj * 128 + tx * 8;
        *(float4*)(dst)     = make_float4(dmat[m][0], dmat[m][1], dmat[m][2], dmat[m][3]);
        *(float4*)(dst + 4) = make_float4(dmat[m][4], dmat[m][5], dmat[m][6], dmat[m][7]);
    }
    if (bi != bj) {
#pragma unroll
        for (int n = 0; n < 8; n++) {
            int gj = bj * 128 + tx * 8 + n;
            float* dst = D + (size_t)gj * NPTS + bi * 128 + ty * 8;
            *(float4*)(dst)     = make_float4(dmat[0][n], dmat[1][n], dmat[2][n], dmat[3][n]);
            *(float4*)(dst + 4) = make_float4(dmat[4][n], dmat[5][n], dmat[6][n], dmat[7][n]);
        }
    }

    if (which == 0) {
        int lane = tid & 31, wid = tid >> 5;
#pragma unroll
        for (int off = 16; off; off >>= 1)
            lmax = fmaxf(lmax, __shfl_down_sync(0xffffffffu, lmax, off));
        __shared__ float smax[8];
        if (lane == 0) smax[wid] = lmax;
        __syncthreads();
        if (tid == 0) {
            float mx = smax[0];
#pragma unroll
            for (int w = 1; w < 8; w++) mx = fmaxf(mx, smax[w]);
            atomicMax(&g_dmax_bits, __float_as_uint(mx));
        }
    }
}

// ---- Boruvka scan over fp32 matrix with monotone cache ----
// grid (512, 2): one warp per row, 8 rows per 256-thread block.
// Cache rule: if the row's cached best target is still outside the row's
// component, the cached edge is still the row's min outgoing edge -> skip.
__global__ void __launch_bounds__(256) boruvka_scan() {
    int m = blockIdx.y;
    if (g_done[m]) return;
    const float* __restrict__ dist = (m == 0) ? g_ddist : g_ldist;
    const int* __restrict__ comp = g_comp[m];

    __shared__ __align__(16) int scomp[NPTS];
    for (int t = threadIdx.x; t < NPTS; t += 256) scomp[t] = comp[t];
    __syncthreads();

    int w = threadIdx.x >> 5, lane = threadIdx.x & 31;
    int row = blockIdx.x * 8 + w;
    int mycomp = scomp[row];

    // monotone cache check (uniform across the warp)
    {
        unsigned long long nb = g_nbest[m][row];
        int pj = (int)(nb & 0xFFF);
        if (scomp[pj] != mycomp) return;   // cached best still outgoing -> keep
    }

    const float4* __restrict__ rp = (const float4*)(dist + (size_t)row * NPTS);
    const int4* __restrict__ cp = (const int4*)scomp;

    unsigned bestv = 0xFFFFFFFFu;
    int bestj = 0;
#pragma unroll 8
    for (int k = 0; k < 32; k++) {
        int c4 = k * 32 + lane;
        float4 v = rp[c4];
        int4 cc = cp[c4];
        int col = c4 << 2;
        unsigned b;
        b = __float_as_uint(v.x); if (cc.x != mycomp && b < bestv) { bestv = b; bestj = col; }
        b = __float_as_uint(v.y); if (cc.y != mycomp && b < bestv) { bestv = b; bestj = col + 1; }
        b = __float_as_uint(v.z); if (cc.z != mycomp && b < bestv) { bestv = b; bestj = col + 2; }
        b = __float_as_uint(v.w); if (cc.w != mycomp && b < bestv) { bestv = b; bestj = col + 3; }
    }
    unsigned rv = __reduce_min_sync(0xffffffffu, bestv);
    unsigned rj = __reduce_min_sync(0xffffffffu,
                                    (bestv == rv) ? (unsigned)bestj : 0xFFFFFFFFu);
    if (lane == 0)
        g_nbest[m][row] = ((unsigned long long)rv << 24)
                        | ((unsigned long long)row << 12)
                        | (unsigned long long)rj;
}

// ---- Boruvka merge: per-comp best, hook, pointer-jump, relabel ----
__global__ void __launch_bounds__(1024) boruvka_merge() {
    int m = blockIdx.x;
    if (g_done[m]) return;
    __shared__ __align__(8) unsigned long long table[NPTS];
    __shared__ int scnt;
    int tid = threadIdx.x;
    int* __restrict__ parent = g_parent[m];
    const int* __restrict__ comp = g_comp[m];

    for (int c = tid; c < NPTS; c += 1024) { table[c] = ~0ull; parent[c] = c; }
    if (tid == 0) scnt = 0;
    __syncthreads();

    for (int n = tid; n < NPTS; n += 1024)
        atomicMin(&table[comp[n]], g_nbest[m][n]);
    __syncthreads();

    for (int c = tid; c < NPTS; c += 1024) {
        unsigned long long e = table[c];
        if (e != ~0ull) {
            int i = (int)((e >> 12) & 0xFFF);
            int j = (int)(e & 0xFFF);
            int t = comp[j];
            unsigned long long et = table[t];
            int i2 = (int)((et >> 12) & 0xFFF);
            int j2 = (int)(et & 0xFFF);
            bool mutual = (i2 == j) && (j2 == i);
            if (!mutual || c < t) {
                int pos = atomicAdd(&g_ecnt[m], 1);
                g_edges[m][2 * pos]     = i;
                g_edges[m][2 * pos + 1] = j;
            }
            parent[c] = (mutual && c < t) ? c : t;
        }
    }
    __syncthreads();

    for (int it = 0; it < 12; it++) {
        for (int c = tid; c < NPTS; c += 1024) {
            int p = parent[c];
            parent[c] = parent[p];
        }
        __syncthreads();
    }

    int* mark = (int*)table;
    for (int c = tid; c < NPTS; c += 1024) mark[c] = 0;
    __syncthreads();
    for (int n = tid; n < NPTS; n += 1024) {
        int r = parent[comp[n]];
        g_comp[m][n] = r;
        mark[r] = 1;
    }
    __syncthreads();
    int cnt = 0;
    for (int c = tid; c < NPTS; c += 1024) cnt += mark[c];
#pragma unroll
    for (int off = 16; off; off >>= 1) cnt += __shfl_down_sync(0xffffffffu, cnt, off);
    if ((tid & 31) == 0) atomicAdd(&scnt, cnt);
    __syncthreads();
    if (tid == 0 && scnt == 1) g_done[m] = 1;
}

// ---- gather MST edges from fp32 matrices, compute topo loss (R2-proven) ----
__global__ void __launch_bounds__(1024) topo_kernel(const float* __restrict__ lnorm) {
    int tid = threadIdx.x;
    float invmax = 1.0f / __uint_as_float(g_dmax_bits);
    float invln = 1.0f / lnorm[0];
    float sd = 0.f, sl = 0.f;
    for (int e = tid; e < NEDGE; e += 1024) {
        int u = g_edges[0][2 * e], v = g_edges[0][2 * e + 1];
        size_t o = (size_t)u * NPTS + v;
        float t = g_ddist[o] * invmax - g_ldist[o] * invln;
        sd += t * t;
        u = g_edges[1][2 * e]; v = g_edges[1][2 * e + 1];
        o = (size_t)u * NPTS + v;
        t = g_ddist[o] * invmax - g_ldist[o] * invln;
        sl += t * t;
    }
#pragma unroll
    for (int off = 16; off; off >>= 1) {
        sd += __shfl_down_sync(0xffffffffu, sd, off);
        sl += __shfl_down_sync(0xffffffffu, sl, off);
    }
    __shared__ float ssd[32], ssl[32];
    if ((tid & 31) == 0) { ssd[tid >> 5] = sd; ssl[tid >> 5] = sl; }
    __syncthreads();
    if (tid < 32) {
        sd = ssd[tid]; sl = ssl[tid];
#pragma unroll
        for (int off = 16; off; off >>= 1) {
            sd += __shfl_down_sync(0xffffffffu, sd, off);
            sl += __shfl_down_sync(0xffffffffu, sl, off);
        }
        if (tid == 0) g_topo = (sd + sl) * (1.0f / NEDGE);
    }
}

__global__ void final_kernel(float* __restrict__ out) {
    int i = blockIdx.x * blockDim.x + threadIdx.x;
    if (i < NPTS) out[i] = g_ae[i] + 0.5f * g_topo;
}

extern "C" void kernel_launch(void* const* d_in, const int* in_sizes, int n_in,
                              void* d_out, int out_size) {
    const float* y_true      = (const float*)d_in[0];
    const float* latent      = (const float*)d_in[1];
    const float* y_pred      = (const float*)d_in[2];
    const float* latent_norm = (const float*)d_in[3];
    float* out = (float*)d_out;

    init_kernel<<<16, 256>>>();
    ae_sq_kernel<<<NPTS, 256>>>(y_true, y_pred);
    sq_lat_kernel<<<NPTS, 32>>>(latent);
    gram_kernel<<<dim3(33, 32), 256>>>(y_true, latent);
    for (int r = 0; r < ROUNDS; r++) {
        boruvka_scan<<<dim3(512, 2), 256>>>();
        boruvka_merge<<<2, 1024>>>();
    }
    topo_kernel<<<1, 1024>>>(latent_norm);
    final_kernel<<<16, 256>>>(out);
}

// round 13
// speedup vs baseline: 1.3814x; 1.3814x over previous
#include <cuda_runtime.h>
#include <cuda_bf16.h>
#include <mma.h>
#include <math_constants.h>

#define NPTS 4096
#define DDATA 1024
#define DLAT 64
#define NEDGE (NPTS - 1)
#define ROUNDS 12
#define SLD 40   // smem row stride in bf16 elems (80 B)

using namespace nvcuda;

// ---- scratch (no allocations allowed: device globals) ----
static __device__ float g_ddist[(size_t)NPTS * NPTS];   // raw data distances fp32
static __device__ float g_ldist[(size_t)NPTS * NPTS];   // raw latent distances fp32
static __device__ float g_sqd[NPTS];
static __device__ float g_sql[NPTS];
static __device__ float g_ae[NPTS];
static __device__ int   g_edges[2][NEDGE * 2];
static __device__ int   g_ecnt[2];
static __device__ int   g_done[2];
static __device__ int   g_comp[2][NPTS];
static __device__ int   g_parent[2][NPTS];
static __device__ unsigned long long g_nbest[2][NPTS];
static __device__ unsigned g_dmax_bits;
static __device__ float g_topo;

__global__ void init_kernel() {
    int i = blockIdx.x * blockDim.x + threadIdx.x;
    if (i < NPTS) {
        g_comp[0][i] = i; g_comp[1][i] = i;
        // self-pointing sentinel: target inside own component -> forces round-0 scan
        g_nbest[0][i] = ((unsigned long long)i << 12) | (unsigned long long)i;
        g_nbest[1][i] = ((unsigned long long)i << 12) | (unsigned long long)i;
    }
    if (i == 0) {
        g_dmax_bits = 0u;
        g_ecnt[0] = 0; g_ecnt[1] = 0;
        g_done[0] = 0; g_done[1] = 0;
    }
}

// ---- AE loss + squared norms of y_true (one block per row) ----
__global__ void __launch_bounds__(256) ae_sq_kernel(
    const float* __restrict__ yt, const float* __restrict__ yp) {
    int row = blockIdx.x, tid = threadIdx.x;
    float4 a = ((const float4*)(yt + (size_t)row * DDATA))[tid];
    float4 b = ((const float4*)(yp + (size_t)row * DDATA))[tid];
    float dx = a.x - b.x, dy = a.y - b.y, dz = a.z - b.z, dw = a.w - b.w;
    float ae = dx * dx + dy * dy + dz * dz + dw * dw;
    float sq = a.x * a.x + a.y * a.y + a.z * a.z + a.w * a.w;
#pragma unroll
    for (int off = 16; off; off >>= 1) {
        ae += __shfl_down_sync(0xffffffffu, ae, off);
        sq += __shfl_down_sync(0xffffffffu, sq, off);
    }
    __shared__ float sae[8], ssq[8];
    if ((tid & 31) == 0) { sae[tid >> 5] = ae; ssq[tid >> 5] = sq; }
    __syncthreads();
    if (tid < 8) {
        ae = sae[tid]; sq = ssq[tid];
#pragma unroll
        for (int off = 4; off; off >>= 1) {
            ae += __shfl_down_sync(0xffu, ae, off);
            sq += __shfl_down_sync(0xffu, sq, off);
        }
        if (tid == 0) { g_ae[row] = ae * (1.0f / DDATA); g_sqd[row] = sq; }
    }
}

// ---- squared norms of latent rows (one warp per row) ----
__global__ void __launch_bounds__(32) sq_lat_kernel(const float* __restrict__ lat) {
    int row = blockIdx.x, tid = threadIdx.x;
    float2 v = ((const float2*)(lat + (size_t)row * DLAT))[tid];
    float s = v.x * v.x + v.y * v.y;
#pragma unroll
    for (int off = 16; off; off >>= 1) s += __shfl_down_sync(0xffffffffu, s, off);
    if (tid == 0) g_sql[row] = s;
}

// ---- fused tensor-core gram -> Euclidean distance matrices (fp32 out) ----
// grid (33, 32): bx<32 & by<=bx -> data tile (by,bx); bx<32 & by>bx -> latent
// tile (bx,by); bx==32 -> latent diagonal tile (by,by).
// 128x128 block tile, 8 warps (32x64 warp tile), wmma bf16 m16n16k16.
// bf16-split on the fly: fp32 tiles loaded from the ORIGINAL inputs (proven
// R12 access pattern), split to hi/lo bf16 in-register, staged to 4 smem
// tiles; 3 accumulation passes per chunk: hi*hi + hi*lo + lo*hi (R4-proven
// numerics: rel_err 8.9e-9). KC=32.
__global__ void __launch_bounds__(256) gram_kernel(
    const float* __restrict__ Yd, const float* __restrict__ Yl) {
    int bx = blockIdx.x, by = blockIdx.y;
    int bi, bj, which;
    if (bx < 32) {
        if (by <= bx) { which = 0; bi = by; bj = bx; }
        else          { which = 1; bi = bx; bj = by; }
    } else            { which = 1; bi = by; bj = by; }
    const float* __restrict__ X  = which ? Yl : Yd;
    const int K = which ? DLAT : DDATA;
    const float* __restrict__ sq = which ? g_sql : g_sqd;
    float* __restrict__ D = which ? g_ldist : g_ddist;

    __shared__ __align__(16) __nv_bfloat16 Ahi[128 * SLD];
    __shared__ __align__(16) __nv_bfloat16 Alo[128 * SLD];
    __shared__ __align__(16) __nv_bfloat16 Bhi[128 * SLD];
    __shared__ __align__(16) __nv_bfloat16 Blo[128 * SLD];

    int tid = threadIdx.x, lane = tid & 31, wid = tid >> 5;
    int wm = wid & 3;        // m offset = wm*32
    int wn = wid >> 2;       // n offset = wn*64

    wmma::fragment<wmma::accumulator, 16, 16, 16, float> acc[2][4];
#pragma unroll
    for (int mi = 0; mi < 2; mi++)
#pragma unroll
        for (int ni = 0; ni < 4; ni++) wmma::fill_fragment(acc[mi][ni], 0.0f);

    int lr = tid >> 1;              // 0..127
    int lk = (tid & 1) << 2;        // 0 or 4
    const float* Ap = X + (size_t)(bi * 128 + lr) * K;
    const float* Bp = X + (size_t)(bj * 128 + lr) * K;

    for (int k0 = 0; k0 < K; k0 += 32) {
        __syncthreads();   // protect previous chunk's MMA reads
#pragma unroll
        for (int i = 0; i < 4; i++) {
            int ke = lk + i * 8;
            float4 a = *(const float4*)(Ap + k0 + ke);
            float4 b = *(const float4*)(Bp + k0 + ke);
            __nv_bfloat162 ah01(__float2bfloat16(a.x), __float2bfloat16(a.y));
            __nv_bfloat162 ah23(__float2bfloat16(a.z), __float2bfloat16(a.w));
            __nv_bfloat162 al01(
                __float2bfloat16(a.x - __bfloat162float(ah01.x)),
                __float2bfloat16(a.y - __bfloat162float(ah01.y)));
            __nv_bfloat162 al23(
                __float2bfloat16(a.z - __bfloat162float(ah23.x)),
                __float2bfloat16(a.w - __bfloat162float(ah23.y)));
            __nv_bfloat162 bh01(__float2bfloat16(b.x), __float2bfloat16(b.y));
            __nv_bfloat162 bh23(__float2bfloat16(b.z), __float2bfloat16(b.w));
            __nv_bfloat162 bl01(
                __float2bfloat16(b.x - __bfloat162float(bh01.x)),
                __float2bfloat16(b.y - __bfloat162float(bh01.y)));
            __nv_bfloat162 bl23(
                __float2bfloat16(b.z - __bfloat162float(bh23.x)),
                __float2bfloat16(b.w - __bfloat162float(bh23.y)));
            unsigned long long vah, val, vbh, vbl;
            ((__nv_bfloat162*)&vah)[0] = ah01; ((__nv_bfloat162*)&vah)[1] = ah23;
            ((__nv_bfloat162*)&val)[0] = al01; ((__nv_bfloat162*)&val)[1] = al23;
            ((__nv_bfloat162*)&vbh)[0] = bh01; ((__nv_bfloat162*)&vbh)[1] = bh23;
            ((__nv_bfloat162*)&vbl)[0] = bl01; ((__nv_bfloat162*)&vbl)[1] = bl23;
            *(unsigned long long*)(Ahi + lr * SLD + ke) = vah;
            *(unsigned long long*)(Alo + lr * SLD + ke) = val;
            *(unsigned long long*)(Bhi + lr * SLD + ke) = vbh;
            *(unsigned long long*)(Blo + lr * SLD + ke) = vbl;
        }
        __syncthreads();

#pragma unroll
        for (int kk = 0; kk < 32; kk += 16) {
            wmma::fragment<wmma::matrix_a, 16, 16, 16, __nv_bfloat16, wmma::row_major> ah[2], al[2];
#pragma unroll
            for (int mi = 0; mi < 2; mi++) {
                wmma::load_matrix_sync(ah[mi], Ahi + (wm * 32 + mi * 16) * SLD + kk, SLD);
                wmma::load_matrix_sync(al[mi], Alo + (wm * 32 + mi * 16) * SLD + kk, SLD);
            }
#pragma unroll
            for (int ni = 0; ni < 4; ni++) {
                wmma::fragment<wmma::matrix_b, 16, 16, 16, __nv_bfloat16, wmma::col_major> bh, bl;
                wmma::load_matrix_sync(bh, Bhi + (wn * 64 + ni * 16) * SLD + kk, SLD);
                wmma::load_matrix_sync(bl, Blo + (wn * 64 + ni * 16) * SLD + kk, SLD);
#pragma unroll
                for (int mi = 0; mi < 2; mi++) {
                    wmma::mma_sync(acc[mi][ni], ah[mi], bh, acc[mi][ni]);
                    wmma::mma_sync(acc[mi][ni], ah[mi], bl, acc[mi][ni]);
                    wmma::mma_sync(acc[mi][ni], al[mi], bh, acc[mi][ni]);
                }
            }
        }
    }
    __syncthreads();   // before reusing Ahi as epilogue staging

    // epilogue (R4-proven staging): d = sqrt(max(sq_i+sq_j-2g, 0)), fp32 out
    float* sc = (float*)Ahi;   // 8 warps x 256 floats = 8 KB
    float lmax = 0.f;
#pragma unroll
    for (int mi = 0; mi < 2; mi++) {
#pragma unroll
        for (int ni = 0; ni < 4; ni++) {
            wmma::store_matrix_sync(sc + wid * 256, acc[mi][ni], 16, wmma::mem_row_major);
            __syncwarp();
            int m0 = bi * 128 + wm * 32 + mi * 16;
            int n0 = bj * 128 + wn * 64 + ni * 16;
            int r = lane >> 1;
            int c0 = (lane & 1) << 3;
            float sqa = sq[m0 + r];
#pragma unroll
            for (int t = 0; t < 8; t++) {
                int c = c0 + t;
                float g = sc[wid * 256 + r * 16 + c];
                int gi = m0 + r, gj = n0 + c;
                float d2 = sqa + sq[gj] - 2.0f * g;
                float d = (d2 > 0.f) ? sqrtf(d2) : 0.f;
                D[(size_t)gi * NPTS + gj] = d;
                if (bi != bj) D[(size_t)gj * NPTS + gi] = d;
                lmax = fmaxf(lmax, d);
            }
            __syncwarp();
        }
    }

    if (which == 0) {
#pragma unroll
        for (int off = 16; off; off >>= 1)
            lmax = fmaxf(lmax, __shfl_down_sync(0xffffffffu, lmax, off));
        __shared__ float smax[8];
        if (lane == 0) smax[wid] = lmax;
        __syncthreads();
        if (tid == 0) {
            float mx = smax[0];
#pragma unroll
            for (int w = 1; w < 8; w++) mx = fmaxf(mx, smax[w]);
            atomicMax(&g_dmax_bits, __float_as_uint(mx));
        }
    }
}

// ---- Boruvka scan over fp32 matrix with monotone cache ----
// grid (512, 2): one warp per row, 8 rows per 256-thread block.
__global__ void __launch_bounds__(256) boruvka_scan() {
    int m = blockIdx.y;
    if (g_done[m]) return;
    const float* __restrict__ dist = (m == 0) ? g_ddist : g_ldist;
    const int* __restrict__ comp = g_comp[m];

    __shared__ __align__(16) int scomp[NPTS];
    for (int t = threadIdx.x; t < NPTS; t += 256) scomp[t] = comp[t];
    __syncthreads();

    int w = threadIdx.x >> 5, lane = threadIdx.x & 31;
    int row = blockIdx.x * 8 + w;
    int mycomp = scomp[row];

    // monotone cache check (uniform across the warp)
    {
        unsigned long long nb = g_nbest[m][row];
        int pj = (int)(nb & 0xFFF);
        if (scomp[pj] != mycomp) return;   // cached best still outgoing -> keep
    }

    const float4* __restrict__ rp = (const float4*)(dist + (size_t)row * NPTS);
    const int4* __restrict__ cp = (const int4*)scomp;

    unsigned bestv = 0xFFFFFFFFu;
    int bestj = 0;
#pragma unroll 8
    for (int k = 0; k < 32; k++) {
        int c4 = k * 32 + lane;
        float4 v = rp[c4];
        int4 cc = cp[c4];
        int col = c4 << 2;
        unsigned b;
        b = __float_as_uint(v.x); if (cc.x != mycomp && b < bestv) { bestv = b; bestj = col; }
        b = __float_as_uint(v.y); if (cc.y != mycomp && b < bestv) { bestv = b; bestj = col + 1; }
        b = __float_as_uint(v.z); if (cc.z != mycomp && b < bestv) { bestv = b; bestj = col + 2; }
        b = __float_as_uint(v.w); if (cc.w != mycomp && b < bestv) { bestv = b; bestj = col + 3; }
    }
    unsigned rv = __reduce_min_sync(0xffffffffu, bestv);
    unsigned rj = __reduce_min_sync(0xffffffffu,
                                    (bestv == rv) ? (unsigned)bestj : 0xFFFFFFFFu);
    if (lane == 0)
        g_nbest[m][row] = ((unsigned long long)rv << 24)
                        | ((unsigned long long)row << 12)
                        | (unsigned long long)rj;
}

// ---- Boruvka merge: per-comp best, hook, pointer-jump, relabel ----
__global__ void __launch_bounds__(1024) boruvka_merge() {
    int m = blockIdx.x;
    if (g_done[m]) return;
    __shared__ __align__(8) unsigned long long table[NPTS];
    __shared__ int scnt;
    int tid = threadIdx.x;
    int* __restrict__ parent = g_parent[m];
    const int* __restrict__ comp = g_comp[m];

    for (int c = tid; c < NPTS; c += 1024) { table[c] = ~0ull; parent[c] = c; }
    if (tid == 0) scnt = 0;
    __syncthreads();

    for (int n = tid; n < NPTS; n += 1024)
        atomicMin(&table[comp[n]], g_nbest[m][n]);
    __syncthreads();

    for (int c = tid; c < NPTS; c += 1024) {
        unsigned long long e = table[c];
        if (e != ~0ull) {
            int i = (int)((e >> 12) & 0xFFF);
            int j = (int)(e & 0xFFF);
            int t = comp[j];
            unsigned long long et = table[t];
            int i2 = (int)((et >> 12) & 0xFFF);
            int j2 = (int)(et & 0xFFF);
            bool mutual = (i2 == j) && (j2 == i);
            if (!mutual || c < t) {
                int pos = atomicAdd(&g_ecnt[m], 1);
                g_edges[m][2 * pos]     = i;
                g_edges[m][2 * pos + 1] = j;
            }
            parent[c] = (mutual && c < t) ? c : t;
        }
    }
    __syncthreads();

    for (int it = 0; it < 12; it++) {
        for (int c = tid; c < NPTS; c += 1024) {
            int p = parent[c];
            parent[c] = parent[p];
        }
        __syncthreads();
    }

    int* mark = (int*)table;
    for (int c = tid; c < NPTS; c += 1024) mark[c] = 0;
    __syncthreads();
    for (int n = tid; n < NPTS; n += 1024) {
        int r = parent[comp[n]];
        g_comp[m][n] = r;
        mark[r] = 1;
    }
    __syncthreads();
    int cnt = 0;
    for (int c = tid; c < NPTS; c += 1024) cnt += mark[c];
#pragma unroll
    for (int off = 16; off; off >>= 1) cnt += __shfl_down_sync(0xffffffffu, cnt, off);
    if ((tid & 31) == 0) atomicAdd(&scnt, cnt);
    __syncthreads();
    if (tid == 0 && scnt == 1) g_done[m] = 1;
}

// ---- gather MST edges from fp32 matrices, compute topo loss ----
__global__ void __launch_bounds__(1024) topo_kernel(const float* __restrict__ lnorm) {
    int tid = threadIdx.x;
    float invmax = 1.0f / __uint_as_float(g_dmax_bits);
    float invln = 1.0f / lnorm[0];
    float sd = 0.f, sl = 0.f;
    for (int e = tid; e < NEDGE; e += 1024) {
        int u = g_edges[0][2 * e], v = g_edges[0][2 * e + 1];
        size_t o = (size_t)u * NPTS + v;
        float t = g_ddist[o] * invmax - g_ldist[o] * invln;
        sd += t * t;
        u = g_edges[1][2 * e]; v = g_edges[1][2 * e + 1];
        o = (size_t)u * NPTS + v;
        t = g_ddist[o] * invmax - g_ldist[o] * invln;
        sl += t * t;
    }
#pragma unroll
    for (int off = 16; off; off >>= 1) {
        sd += __shfl_down_sync(0xffffffffu, sd, off);
        sl += __shfl_down_sync(0xffffffffu, sl, off);
    }
    __shared__ float ssd[32], ssl[32];
    if ((tid & 31) == 0) { ssd[tid >> 5] = sd; ssl[tid >> 5] = sl; }
    __syncthreads();
    if (tid < 32) {
        sd = ssd[tid]; sl = ssl[tid];
#pragma unroll
        for (int off = 16; off; off >>= 1) {
            sd += __shfl_down_sync(0xffffffffu, sd, off);
            sl += __shfl_down_sync(0xffffffffu, sl, off);
        }
        if (tid == 0) g_topo = (sd + sl) * (1.0f / NEDGE);
    }
}

__global__ void final_kernel(float* __restrict__ out) {
    int i = blockIdx.x * blockDim.x + threadIdx.x;
    if (i < NPTS) out[i] = g_ae[i] + 0.5f * g_topo;
}

extern "C" void kernel_launch(void* const* d_in, const int* in_sizes, int n_in,
                              void* d_out, int out_size) {
    const float* y_true      = (const float*)d_in[0];
    const float* latent      = (const float*)d_in[1];
    const float* y_pred      = (const float*)d_in[2];
    const float* latent_norm = (const float*)d_in[3];
    float* out = (float*)d_out;

    init_kernel<<<16, 256>>>();
    ae_sq_kernel<<<NPTS, 256>>>(y_true, y_pred);
    sq_lat_kernel<<<NPTS, 32>>>(latent);
    gram_kernel<<<dim3(33, 32), 256>>>(y_true, latent);
    for (int r = 0; r < ROUNDS; r++) {
        boruvka_scan<<<dim3(512, 2), 256>>>();
        boruvka_merge<<<2, 1024>>>();
    }
    topo_kernel<<<1, 1024>>>(latent_norm);
    final_kernel<<<16, 256>>>(out);
}

// round 14
// speedup vs baseline: 1.4312x; 1.0361x over previous
#include <cuda_runtime.h>
#include <cuda_bf16.h>
#include <mma.h>
#include <math_constants.h>

#define NPTS 4096
#define DDATA 1024
#define DLAT 64
#define NEDGE (NPTS - 1)
#define ROUNDS 12
#define SLD 40                  // smem row stride in bf16 elems (80 B)
#define STG (128 * SLD)         // one tile: 5120 bf16 = 10240 B
#define GRAM_SMEM (2 * 4 * STG * 2)  // 2 stages x 4 tiles x 10240 B = 81920 B

using namespace nvcuda;

// ---- scratch (no allocations allowed: device globals) ----
static __device__ float g_ddist[(size_t)NPTS * NPTS];   // raw data distances fp32
static __device__ float g_ldist[(size_t)NPTS * NPTS];   // raw latent distances fp32
static __device__ float g_sqd[NPTS];
static __device__ float g_sql[NPTS];
static __device__ float g_ae[NPTS];
static __device__ int   g_edges[2][NEDGE * 2];
static __device__ int   g_ecnt[2];
static __device__ int   g_done[2];
static __device__ int   g_comp[2][NPTS];
static __device__ int   g_parent[2][NPTS];
static __device__ unsigned long long g_nbest[2][NPTS];
static __device__ unsigned g_dmax_bits;
static __device__ float g_topo;

__global__ void init_kernel() {
    int i = blockIdx.x * blockDim.x + threadIdx.x;
    if (i < NPTS) {
        g_comp[0][i] = i; g_comp[1][i] = i;
        // self-pointing sentinel: target inside own component -> forces round-0 scan
        g_nbest[0][i] = ((unsigned long long)i << 12) | (unsigned long long)i;
        g_nbest[1][i] = ((unsigned long long)i << 12) | (unsigned long long)i;
    }
    if (i == 0) {
        g_dmax_bits = 0u;
        g_ecnt[0] = 0; g_ecnt[1] = 0;
        g_done[0] = 0; g_done[1] = 0;
    }
}

// ---- AE loss + squared norms of y_true (one block per row) ----
__global__ void __launch_bounds__(256) ae_sq_kernel(
    const float* __restrict__ yt, const float* __restrict__ yp) {
    int row = blockIdx.x, tid = threadIdx.x;
    float4 a = ((const float4*)(yt + (size_t)row * DDATA))[tid];
    float4 b = ((const float4*)(yp + (size_t)row * DDATA))[tid];
    float dx = a.x - b.x, dy = a.y - b.y, dz = a.z - b.z, dw = a.w - b.w;
    float ae = dx * dx + dy * dy + dz * dz + dw * dw;
    float sq = a.x * a.x + a.y * a.y + a.z * a.z + a.w * a.w;
#pragma unroll
    for (int off = 16; off; off >>= 1) {
        ae += __shfl_down_sync(0xffffffffu, ae, off);
        sq += __shfl_down_sync(0xffffffffu, sq, off);
    }
    __shared__ float sae[8], ssq[8];
    if ((tid & 31) == 0) { sae[tid >> 5] = ae; ssq[tid >> 5] = sq; }
    __syncthreads();
    if (tid < 8) {
        ae = sae[tid]; sq = ssq[tid];
#pragma unroll
        for (int off = 4; off; off >>= 1) {
            ae += __shfl_down_sync(0xffu, ae, off);
            sq += __shfl_down_sync(0xffu, sq, off);
        }
        if (tid == 0) { g_ae[row] = ae * (1.0f / DDATA); g_sqd[row] = sq; }
    }
}

// ---- squared norms of latent rows (one warp per row) ----
__global__ void __launch_bounds__(32) sq_lat_kernel(const float* __restrict__ lat) {
    int row = blockIdx.x, tid = threadIdx.x;
    float2 v = ((const float2*)(lat + (size_t)row * DLAT))[tid];
    float s = v.x * v.x + v.y * v.y;
#pragma unroll
    for (int off = 16; off; off >>= 1) s += __shfl_down_sync(0xffffffffu, s, off);
    if (tid == 0) g_sql[row] = s;
}

// ---- fused tensor-core gram -> Euclidean distance matrices (fp32 out) ----
// grid (33, 32): bx<32 & by<=bx -> data tile (by,bx); bx<32 & by>bx -> latent
// tile (bx,by); bx==32 -> latent diagonal tile (by,by).
// 128x128 block tile, 8 warps (32x64 warp tile), wmma bf16 m16n16k16,
// bf16-split 3-pass (hi*hi + hi*lo + lo*hi, R13-proven: rel_err 8.9e-9).
// R14: double-buffered dynamic smem (2 stages) + register prefetch of raw
// global loads -> one __syncthreads per chunk, LDG latency hidden under MMA.
__global__ void __launch_bounds__(256) gram_kernel(
    const float* __restrict__ Yd, const float* __restrict__ Yl) {
    int bx = blockIdx.x, by = blockIdx.y;
    int bi, bj, which;
    if (bx < 32) {
        if (by <= bx) { which = 0; bi = by; bj = bx; }
        else          { which = 1; bi = bx; bj = by; }
    } else            { which = 1; bi = by; bj = by; }
    const float* __restrict__ X  = which ? Yl : Yd;
    const int K = which ? DLAT : DDATA;
    const float* __restrict__ sq = which ? g_sql : g_sqd;
    float* __restrict__ D = which ? g_ldist : g_ddist;

    extern __shared__ __align__(16) __nv_bfloat16 smbuf[];   // 2 stages x 4 tiles

    int tid = threadIdx.x, lane = tid & 31, wid = tid >> 5;
    int wm = wid & 3;        // m offset = wm*32
    int wn = wid >> 2;       // n offset = wn*64

    wmma::fragment<wmma::accumulator, 16, 16, 16, float> acc[2][4];
#pragma unroll
    for (int mi = 0; mi < 2; mi++)
#pragma unroll
        for (int ni = 0; ni < 4; ni++) wmma::fill_fragment(acc[mi][ni], 0.0f);

    int lr = tid >> 1;              // 0..127
    int lk = (tid & 1) << 2;        // 0 or 4
    const float* Ap = X + (size_t)(bi * 128 + lr) * K;
    const float* Bp = X + (size_t)(bj * 128 + lr) * K;

    const int NC = K / 32;
    uint4 pa[4], pb[4];
    // prefetch chunk 0
#pragma unroll
    for (int i = 0; i < 4; i++) {
        pa[i] = *(const uint4*)(Ap + lk + i * 8);
        pb[i] = *(const uint4*)(Bp + lk + i * 8);
    }

#pragma unroll 1
    for (int c = 0; c < NC; c++) {
        __nv_bfloat16* Ahi = smbuf + (c & 1) * 4 * STG;
        __nv_bfloat16* Alo = Ahi + STG;
        __nv_bfloat16* Bhi = Ahi + 2 * STG;
        __nv_bfloat16* Blo = Ahi + 3 * STG;

        // convert prefetched regs -> smem stage (c&1)
#pragma unroll
        for (int i = 0; i < 4; i++) {
            int ke = lk + i * 8;
            float4 a = *(const float4*)&pa[i];
            float4 b = *(const float4*)&pb[i];
            __nv_bfloat162 ah01(__float2bfloat16(a.x), __float2bfloat16(a.y));
            __nv_bfloat162 ah23(__float2bfloat16(a.z), __float2bfloat16(a.w));
            __nv_bfloat162 al01(
                __float2bfloat16(a.x - __bfloat162float(ah01.x)),
                __float2bfloat16(a.y - __bfloat162float(ah01.y)));
            __nv_bfloat162 al23(
                __float2bfloat16(a.z - __bfloat162float(ah23.x)),
                __float2bfloat16(a.w - __bfloat162float(ah23.y)));
            __nv_bfloat162 bh01(__float2bfloat16(b.x), __float2bfloat16(b.y));
            __nv_bfloat162 bh23(__float2bfloat16(b.z), __float2bfloat16(b.w));
            __nv_bfloat162 bl01(
                __float2bfloat16(b.x - __bfloat162float(bh01.x)),
                __float2bfloat16(b.y - __bfloat162float(bh01.y)));
            __nv_bfloat162 bl23(
                __float2bfloat16(b.z - __bfloat162float(bh23.x)),
                __float2bfloat16(b.w - __bfloat162float(bh23.y)));
            unsigned long long vah, val, vbh, vbl;
            ((__nv_bfloat162*)&vah)[0] = ah01; ((__nv_bfloat162*)&vah)[1] = ah23;
            ((__nv_bfloat162*)&val)[0] = al01; ((__nv_bfloat162*)&val)[1] = al23;
            ((__nv_bfloat162*)&vbh)[0] = bh01; ((__nv_bfloat162*)&vbh)[1] = bh23;
            ((__nv_bfloat162*)&vbl)[0] = bl01; ((__nv_bfloat162*)&vbl)[1] = bl23;
            *(unsigned long long*)(Ahi + lr * SLD + ke) = vah;
            *(unsigned long long*)(Alo + lr * SLD + ke) = val;
            *(unsigned long long*)(Bhi + lr * SLD + ke) = vbh;
            *(unsigned long long*)(Blo + lr * SLD + ke) = vbl;
        }
        __syncthreads();

        // prefetch chunk c+1 (LDG latency hides under the MMA block below)
        if (c + 1 < NC) {
            int k1 = (c + 1) * 32;
#pragma unroll
            for (int i = 0; i < 4; i++) {
                pa[i] = *(const uint4*)(Ap + k1 + lk + i * 8);
                pb[i] = *(const uint4*)(Bp + k1 + lk + i * 8);
            }
        }

#pragma unroll
        for (int kk = 0; kk < 32; kk += 16) {
            wmma::fragment<wmma::matrix_a, 16, 16, 16, __nv_bfloat16, wmma::row_major> ah[2], al[2];
#pragma unroll
            for (int mi = 0; mi < 2; mi++) {
                wmma::load_matrix_sync(ah[mi], Ahi + (wm * 32 + mi * 16) * SLD + kk, SLD);
                wmma::load_matrix_sync(al[mi], Alo + (wm * 32 + mi * 16) * SLD + kk, SLD);
            }
#pragma unroll
            for (int ni = 0; ni < 4; ni++) {
                wmma::fragment<wmma::matrix_b, 16, 16, 16, __nv_bfloat16, wmma::col_major> bh, bl;
                wmma::load_matrix_sync(bh, Bhi + (wn * 64 + ni * 16) * SLD + kk, SLD);
                wmma::load_matrix_sync(bl, Blo + (wn * 64 + ni * 16) * SLD + kk, SLD);
#pragma unroll
                for (int mi = 0; mi < 2; mi++) {
                    wmma::mma_sync(acc[mi][ni], ah[mi], bh, acc[mi][ni]);
                    wmma::mma_sync(acc[mi][ni], ah[mi], bl, acc[mi][ni]);
                    wmma::mma_sync(acc[mi][ni], al[mi], bh, acc[mi][ni]);
                }
            }
        }
    }
    __syncthreads();   // before reusing smbuf as epilogue staging

    // epilogue (R13-proven staging): d = sqrt(max(sq_i+sq_j-2g, 0)), fp32 out
    float* sc = (float*)smbuf;   // 8 warps x 256 floats = 8 KB
    float lmax = 0.f;
#pragma unroll
    for (int mi = 0; mi < 2; mi++) {
#pragma unroll
        for (int ni = 0; ni < 4; ni++) {
            wmma::store_matrix_sync(sc + wid * 256, acc[mi][ni], 16, wmma::mem_row_major);
            __syncwarp();
            int m0 = bi * 128 + wm * 32 + mi * 16;
            int n0 = bj * 128 + wn * 64 + ni * 16;
            int r = lane >> 1;
            int c0 = (lane & 1) << 3;
            float sqa = sq[m0 + r];
#pragma unroll
            for (int t = 0; t < 8; t++) {
                int c = c0 + t;
                float g = sc[wid * 256 + r * 16 + c];
                int gi = m0 + r, gj = n0 + c;
                float d2 = sqa + sq[gj] - 2.0f * g;
                float d = (d2 > 0.f) ? sqrtf(d2) : 0.f;
                D[(size_t)gi * NPTS + gj] = d;
                if (bi != bj) D[(size_t)gj * NPTS + gi] = d;
                lmax = fmaxf(lmax, d);
            }
            __syncwarp();
        }
    }

    if (which == 0) {
#pragma unroll
        for (int off = 16; off; off >>= 1)
            lmax = fmaxf(lmax, __shfl_down_sync(0xffffffffu, lmax, off));
        __shared__ float smax[8];
        if (lane == 0) smax[wid] = lmax;
        __syncthreads();
        if (tid == 0) {
            float mx = smax[0];
#pragma unroll
            for (int w = 1; w < 8; w++) mx = fmaxf(mx, smax[w]);
            atomicMax(&g_dmax_bits, __float_as_uint(mx));
        }
    }
}

// ---- Boruvka scan over fp32 matrix with monotone cache ----
// grid (512, 2): one warp per row, 8 rows per 256-thread block.
__global__ void __launch_bounds__(256) boruvka_scan() {
    int m = blockIdx.y;
    if (g_done[m]) return;
    const float* __restrict__ dist = (m == 0) ? g_ddist : g_ldist;
    const int* __restrict__ comp = g_comp[m];

    __shared__ __align__(16) int scomp[NPTS];
    for (int t = threadIdx.x; t < NPTS; t += 256) scomp[t] = comp[t];
    __syncthreads();

    int w = threadIdx.x >> 5, lane = threadIdx.x & 31;
    int row = blockIdx.x * 8 + w;
    int mycomp = scomp[row];

    // monotone cache check (uniform across the warp)
    {
        unsigned long long nb = g_nbest[m][row];
        int pj = (int)(nb & 0xFFF);
        if (scomp[pj] != mycomp) return;   // cached best still outgoing -> keep
    }

    const float4* __restrict__ rp = (const float4*)(dist + (size_t)row * NPTS);
    const int4* __restrict__ cp = (const int4*)scomp;

    unsigned bestv = 0xFFFFFFFFu;
    int bestj = 0;
#pragma unroll 8
    for (int k = 0; k < 32; k++) {
        int c4 = k * 32 + lane;
        float4 v = rp[c4];
        int4 cc = cp[c4];
        int col = c4 << 2;
        unsigned b;
        b = __float_as_uint(v.x); if (cc.x != mycomp && b < bestv) { bestv = b; bestj = col; }
        b = __float_as_uint(v.y); if (cc.y != mycomp && b < bestv) { bestv = b; bestj = col + 1; }
        b = __float_as_uint(v.z); if (cc.z != mycomp && b < bestv) { bestv = b; bestj = col + 2; }
        b = __float_as_uint(v.w); if (cc.w != mycomp && b < bestv) { bestv = b; bestj = col + 3; }
    }
    unsigned rv = __reduce_min_sync(0xffffffffu, bestv);
    unsigned rj = __reduce_min_sync(0xffffffffu,
                                    (bestv == rv) ? (unsigned)bestj : 0xFFFFFFFFu);
    if (lane == 0)
        g_nbest[m][row] = ((unsigned long long)rv << 24)
                        | ((unsigned long long)row << 12)
                        | (unsigned long long)rj;
}

// ---- Boruvka merge: per-comp best, hook, pointer-jump, relabel ----
__global__ void __launch_bounds__(1024) boruvka_merge() {
    int m = blockIdx.x;
    if (g_done[m]) return;
    __shared__ __align__(8) unsigned long long table[NPTS];
    __shared__ int scnt;
    int tid = threadIdx.x;
    int* __restrict__ parent = g_parent[m];
    const int* __restrict__ comp = g_comp[m];

    for (int c = tid; c < NPTS; c += 1024) { table[c] = ~0ull; parent[c] = c; }
    if (tid == 0) scnt = 0;
    __syncthreads();

    for (int n = tid; n < NPTS; n += 1024)
        atomicMin(&table[comp[n]], g_nbest[m][n]);
    __syncthreads();

    for (int c = tid; c < NPTS; c += 1024) {
        unsigned long long e = table[c];
        if (e != ~0ull) {
            int i = (int)((e >> 12) & 0xFFF);
            int j = (int)(e & 0xFFF);
            int t = comp[j];
            unsigned long long et = table[t];
            int i2 = (int)((et >> 12) & 0xFFF);
            int j2 = (int)(et & 0xFFF);
            bool mutual = (i2 == j) && (j2 == i);
            if (!mutual || c < t) {
                int pos = atomicAdd(&g_ecnt[m], 1);
                g_edges[m][2 * pos]     = i;
                g_edges[m][2 * pos + 1] = j;
            }
            parent[c] = (mutual && c < t) ? c : t;
        }
    }
    __syncthreads();

    for (int it = 0; it < 12; it++) {
        for (int c = tid; c < NPTS; c += 1024) {
            int p = parent[c];
            parent[c] = parent[p];
        }
        __syncthreads();
    }

    int* mark = (int*)table;
    for (int c = tid; c < NPTS; c += 1024) mark[c] = 0;
    __syncthreads();
    for (int n = tid; n < NPTS; n += 1024) {
        int r = parent[comp[n]];
        g_comp[m][n] = r;
        mark[r] = 1;
    }
    __syncthreads();
    int cnt = 0;
    for (int c = tid; c < NPTS; c += 1024) cnt += mark[c];
#pragma unroll
    for (int off = 16; off; off >>= 1) cnt += __shfl_down_sync(0xffffffffu, cnt, off);
    if ((tid & 31) == 0) atomicAdd(&scnt, cnt);
    __syncthreads();
    if (tid == 0 && scnt == 1) g_done[m] = 1;
}

// ---- gather MST edges from fp32 matrices, compute topo loss ----
__global__ void __launch_bounds__(1024) topo_kernel(const float* __restrict__ lnorm) {
    int tid = threadIdx.x;
    float invmax = 1.0f / __uint_as_float(g_dmax_bits);
    float invln = 1.0f / lnorm[0];
    float sd = 0.f, sl = 0.f;
    for (int e = tid; e < NEDGE; e += 1024) {
        int u = g_edges[0][2 * e], v = g_edges[0][2 * e + 1];
        size_t o = (size_t)u * NPTS + v;
        float t = g_ddist[o] * invmax - g_ldist[o] * invln;
        sd += t * t;
        u = g_edges[1][2 * e]; v = g_edges[1][2 * e + 1];
        o = (size_t)u * NPTS + v;
        t = g_ddist[o] * invmax - g_ldist[o] * invln;
        sl += t * t;
    }
#pragma unroll
    for (int off = 16; off; off >>= 1) {
        sd += __shfl_down_sync(0xffffffffu, sd, off);
        sl += __shfl_down_sync(0xffffffffu, sl, off);
    }
    __shared__ float ssd[32], ssl[32];
    if ((tid & 31) == 0) { ssd[tid >> 5] = sd; ssl[tid >> 5] = sl; }
    __syncthreads();
    if (tid < 32) {
        sd = ssd[tid]; sl = ssl[tid];
#pragma unroll
        for (int off = 16; off; off >>= 1) {
            sd += __shfl_down_sync(0xffffffffu, sd, off);
            sl += __shfl_down_sync(0xffffffffu, sl, off);
        }
        if (tid == 0) g_topo = (sd + sl) * (1.0f / NEDGE);
    }
}

__global__ void final_kernel(float* __restrict__ out) {
    int i = blockIdx.x * blockDim.x + threadIdx.x;
    if (i < NPTS) out[i] = g_ae[i] + 0.5f * g_topo;
}

extern "C" void kernel_launch(void* const* d_in, const int* in_sizes, int n_in,
                              void* d_out, int out_size) {
    const float* y_true      = (const float*)d_in[0];
    const float* latent      = (const float*)d_in[1];
    const float* y_pred      = (const float*)d_in[2];
    const float* latent_norm = (const float*)d_in[3];
    float* out = (float*)d_out;

    static int attr_set = 0;
    if (!attr_set) {
        cudaFuncSetAttribute(gram_kernel,
                             cudaFuncAttributeMaxDynamicSharedMemorySize,
                             GRAM_SMEM);
        attr_set = 1;
    }

    init_kernel<<<16, 256>>>();
    ae_sq_kernel<<<NPTS, 256>>>(y_true, y_pred);
    sq_lat_kernel<<<NPTS, 32>>>(latent);
    gram_kernel<<<dim3(33, 32), 256, GRAM_SMEM>>>(y_true, latent);
    for (int r = 0; r < ROUNDS; r++) {
        boruvka_scan<<<dim3(512, 2), 256>>>();
        boruvka_merge<<<2, 1024>>>();
    }
    topo_kernel<<<1, 1024>>>(latent_norm);
    final_kernel<<<16, 256>>>(out);
}

// round 15
// speedup vs baseline: 1.5075x; 1.0533x over previous
#include <cuda_runtime.h>
#include <cuda_bf16.h>
#include <mma.h>
#include <math_constants.h>

#define NPTS 4096
#define DDATA 1024
#define DLAT 64
#define NEDGE (NPTS - 1)
#define ROUNDS 12
#define SLD 40                  // smem row stride in bf16 elems (80 B)
#define STG (128 * SLD)         // one tile: 5120 bf16 = 10240 B
#define GRAM_SMEM (2 * 4 * STG * 2)  // 2 stages x 4 tiles x 10240 B = 81920 B

using namespace nvcuda;

// ---- scratch (no allocations allowed: device globals) ----
static __device__ float g_ddist[(size_t)NPTS * NPTS];   // raw data distances fp32
static __device__ float g_ldist[(size_t)NPTS * NPTS];   // raw latent distances fp32
static __device__ float g_sqd[NPTS];
static __device__ float g_sql[NPTS];
static __device__ float g_ae[NPTS];
static __device__ int   g_edges[2][NEDGE * 2];
static __device__ int   g_ecnt[2];
static __device__ int   g_done[2];
static __device__ int   g_comp[2][NPTS];
static __device__ int   g_parent[2][NPTS];
static __device__ unsigned long long g_nbest[2][NPTS];
static __device__ unsigned g_dmax_bits;
static __device__ float g_topo;

__global__ void init_kernel() {
    int i = blockIdx.x * blockDim.x + threadIdx.x;
    if (i < NPTS) {
        g_comp[0][i] = i; g_comp[1][i] = i;
        // self-pointing sentinel: target inside own component -> forces round-0 scan
        g_nbest[0][i] = ((unsigned long long)i << 12) | (unsigned long long)i;
        g_nbest[1][i] = ((unsigned long long)i << 12) | (unsigned long long)i;
    }
    if (i == 0) {
        g_dmax_bits = 0u;
        g_ecnt[0] = 0; g_ecnt[1] = 0;
        g_done[0] = 0; g_done[1] = 0;
    }
}

// ---- AE loss + squared norms of y_true (one block per row) ----
__global__ void __launch_bounds__(256) ae_sq_kernel(
    const float* __restrict__ yt, const float* __restrict__ yp) {
    int row = blockIdx.x, tid = threadIdx.x;
    float4 a = ((const float4*)(yt + (size_t)row * DDATA))[tid];
    float4 b = ((const float4*)(yp + (size_t)row * DDATA))[tid];
    float dx = a.x - b.x, dy = a.y - b.y, dz = a.z - b.z, dw = a.w - b.w;
    float ae = dx * dx + dy * dy + dz * dz + dw * dw;
    float sq = a.x * a.x + a.y * a.y + a.z * a.z + a.w * a.w;
#pragma unroll
    for (int off = 16; off; off >>= 1) {
        ae += __shfl_down_sync(0xffffffffu, ae, off);
        sq += __shfl_down_sync(0xffffffffu, sq, off);
    }
    __shared__ float sae[8], ssq[8];
    if ((tid & 31) == 0) { sae[tid >> 5] = ae; ssq[tid >> 5] = sq; }
    __syncthreads();
    if (tid < 8) {
        ae = sae[tid]; sq = ssq[tid];
#pragma unroll
        for (int off = 4; off; off >>= 1) {
            ae += __shfl_down_sync(0xffu, ae, off);
            sq += __shfl_down_sync(0xffu, sq, off);
        }
        if (tid == 0) { g_ae[row] = ae * (1.0f / DDATA); g_sqd[row] = sq; }
    }
}

// ---- squared norms of latent rows (one warp per row) ----
__global__ void __launch_bounds__(32) sq_lat_kernel(const float* __restrict__ lat) {
    int row = blockIdx.x, tid = threadIdx.x;
    float2 v = ((const float2*)(lat + (size_t)row * DLAT))[tid];
    float s = v.x * v.x + v.y * v.y;
#pragma unroll
    for (int off = 16; off; off >>= 1) s += __shfl_down_sync(0xffffffffu, s, off);
    if (tid == 0) g_sql[row] = s;
}

// ---- fused tensor-core gram -> Euclidean distance matrices (fp32 out) ----
// grid (33, 32): bx<32 & by<=bx -> data tile (by,bx); bx<32 & by>bx -> latent
// tile (bx,by); bx==32 -> latent diagonal tile (by,by).
// R15: 512 threads, 16 warps (32x32 warp tile) to double latency-hiding pool.
// 128x128 block tile, wmma bf16 m16n16k16, bf16-split 3-pass
// (hi*hi + hi*lo + lo*hi, proven: rel_err 8.9e-9), double-buffered smem +
// register prefetch, one __syncthreads per chunk.
__global__ void __launch_bounds__(512) gram_kernel(
    const float* __restrict__ Yd, const float* __restrict__ Yl) {
    int bx = blockIdx.x, by = blockIdx.y;
    int bi, bj, which;
    if (bx < 32) {
        if (by <= bx) { which = 0; bi = by; bj = bx; }
        else          { which = 1; bi = bx; bj = by; }
    } else            { which = 1; bi = by; bj = by; }
    const float* __restrict__ X  = which ? Yl : Yd;
    const int K = which ? DLAT : DDATA;
    const float* __restrict__ sq = which ? g_sql : g_sqd;
    float* __restrict__ D = which ? g_ldist : g_ddist;

    extern __shared__ __align__(16) __nv_bfloat16 smbuf[];   // 2 stages x 4 tiles

    int tid = threadIdx.x, lane = tid & 31, wid = tid >> 5;   // wid 0..15
    int wm = wid & 3;        // m offset = wm*32
    int wn = wid >> 2;       // n offset = wn*32

    wmma::fragment<wmma::accumulator, 16, 16, 16, float> acc[2][2];
#pragma unroll
    for (int mi = 0; mi < 2; mi++)
#pragma unroll
        for (int ni = 0; ni < 2; ni++) wmma::fill_fragment(acc[mi][ni], 0.0f);

    int lr = tid >> 2;              // 0..127
    int lk = (tid & 3) << 3;        // 0,8,16,24
    const float* Ap = X + (size_t)(bi * 128 + lr) * K;
    const float* Bp = X + (size_t)(bj * 128 + lr) * K;

    const int NC = K / 32;
    uint4 pa[2], pb[2];
    // prefetch chunk 0 (each thread: cols [lk, lk+8))
#pragma unroll
    for (int i = 0; i < 2; i++) {
        pa[i] = *(const uint4*)(Ap + lk + i * 4);
        pb[i] = *(const uint4*)(Bp + lk + i * 4);
    }

#pragma unroll 1
    for (int c = 0; c < NC; c++) {
        __nv_bfloat16* Ahi = smbuf + (c & 1) * 4 * STG;
        __nv_bfloat16* Alo = Ahi + STG;
        __nv_bfloat16* Bhi = Ahi + 2 * STG;
        __nv_bfloat16* Blo = Ahi + 3 * STG;

        // convert prefetched regs -> smem stage (c&1)
#pragma unroll
        for (int i = 0; i < 2; i++) {
            int ke = lk + i * 4;
            float4 a = *(const float4*)&pa[i];
            float4 b = *(const float4*)&pb[i];
            __nv_bfloat162 ah01(__float2bfloat16(a.x), __float2bfloat16(a.y));
            __nv_bfloat162 ah23(__float2bfloat16(a.z), __float2bfloat16(a.w));
            __nv_bfloat162 al01(
                __float2bfloat16(a.x - __bfloat162float(ah01.x)),
                __float2bfloat16(a.y - __bfloat162float(ah01.y)));
            __nv_bfloat162 al23(
                __float2bfloat16(a.z - __bfloat162float(ah23.x)),
                __float2bfloat16(a.w - __bfloat162float(ah23.y)));
            __nv_bfloat162 bh01(__float2bfloat16(b.x), __float2bfloat16(b.y));
            __nv_bfloat162 bh23(__float2bfloat16(b.z), __float2bfloat16(b.w));
            __nv_bfloat162 bl01(
                __float2bfloat16(b.x - __bfloat162float(bh01.x)),
                __float2bfloat16(b.y - __bfloat162float(bh01.y)));
            __nv_bfloat162 bl23(
                __float2bfloat16(b.z - __bfloat162float(bh23.x)),
                __float2bfloat16(b.w - __bfloat162float(bh23.y)));
            unsigned long long vah, val, vbh, vbl;
            ((__nv_bfloat162*)&vah)[0] = ah01; ((__nv_bfloat162*)&vah)[1] = ah23;
            ((__nv_bfloat162*)&val)[0] = al01; ((__nv_bfloat162*)&val)[1] = al23;
            ((__nv_bfloat162*)&vbh)[0] = bh01; ((__nv_bfloat162*)&vbh)[1] = bh23;
            ((__nv_bfloat162*)&vbl)[0] = bl01; ((__nv_bfloat162*)&vbl)[1] = bl23;
            *(unsigned long long*)(Ahi + lr * SLD + ke) = vah;
            *(unsigned long long*)(Alo + lr * SLD + ke) = val;
            *(unsigned long long*)(Bhi + lr * SLD + ke) = vbh;
            *(unsigned long long*)(Blo + lr * SLD + ke) = vbl;
        }
        __syncthreads();

        // prefetch chunk c+1 (LDG latency hides under the MMA block below)
        if (c + 1 < NC) {
            int k1 = (c + 1) * 32;
#pragma unroll
            for (int i = 0; i < 2; i++) {
                pa[i] = *(const uint4*)(Ap + k1 + lk + i * 4);
                pb[i] = *(const uint4*)(Bp + k1 + lk + i * 4);
            }
        }

#pragma unroll
        for (int kk = 0; kk < 32; kk += 16) {
            wmma::fragment<wmma::matrix_a, 16, 16, 16, __nv_bfloat16, wmma::row_major> ah[2], al[2];
#pragma unroll
            for (int mi = 0; mi < 2; mi++) {
                wmma::load_matrix_sync(ah[mi], Ahi + (wm * 32 + mi * 16) * SLD + kk, SLD);
                wmma::load_matrix_sync(al[mi], Alo + (wm * 32 + mi * 16) * SLD + kk, SLD);
            }
#pragma unroll
            for (int ni = 0; ni < 2; ni++) {
                wmma::fragment<wmma::matrix_b, 16, 16, 16, __nv_bfloat16, wmma::col_major> bh, bl;
                wmma::load_matrix_sync(bh, Bhi + (wn * 32 + ni * 16) * SLD + kk, SLD);
                wmma::load_matrix_sync(bl, Blo + (wn * 32 + ni * 16) * SLD + kk, SLD);
#pragma unroll
                for (int mi = 0; mi < 2; mi++) {
                    wmma::mma_sync(acc[mi][ni], ah[mi], bh, acc[mi][ni]);
                    wmma::mma_sync(acc[mi][ni], ah[mi], bl, acc[mi][ni]);
                    wmma::mma_sync(acc[mi][ni], al[mi], bh, acc[mi][ni]);
                }
            }
        }
    }
    __syncthreads();   // before reusing smbuf as epilogue staging

    // epilogue: d = sqrt(max(sq_i+sq_j-2g, 0)), fp32 out (16 warps x 256 floats)
    float* sc = (float*)smbuf;
    float lmax = 0.f;
#pragma unroll
    for (int mi = 0; mi < 2; mi++) {
#pragma unroll
        for (int ni = 0; ni < 2; ni++) {
            wmma::store_matrix_sync(sc + wid * 256, acc[mi][ni], 16, wmma::mem_row_major);
            __syncwarp();
            int m0 = bi * 128 + wm * 32 + mi * 16;
            int n0 = bj * 128 + wn * 32 + ni * 16;
            int r = lane >> 1;
            int c0 = (lane & 1) << 3;
            float sqa = sq[m0 + r];
#pragma unroll
            for (int t = 0; t < 8; t++) {
                int c = c0 + t;
                float g = sc[wid * 256 + r * 16 + c];
                int gi = m0 + r, gj = n0 + c;
                float d2 = sqa + sq[gj] - 2.0f * g;
                float d = (d2 > 0.f) ? sqrtf(d2) : 0.f;
                D[(size_t)gi * NPTS + gj] = d;
                if (bi != bj) D[(size_t)gj * NPTS + gi] = d;
                lmax = fmaxf(lmax, d);
            }
            __syncwarp();
        }
    }

    if (which == 0) {
#pragma unroll
        for (int off = 16; off; off >>= 1)
            lmax = fmaxf(lmax, __shfl_down_sync(0xffffffffu, lmax, off));
        __shared__ float smax[16];
        if (lane == 0) smax[wid] = lmax;
        __syncthreads();
        if (tid == 0) {
            float mx = smax[0];
#pragma unroll
            for (int w = 1; w < 16; w++) mx = fmaxf(mx, smax[w]);
            atomicMax(&g_dmax_bits, __float_as_uint(mx));
        }
    }
}

// ---- Boruvka scan over fp32 matrix with monotone cache ----
// grid (512, 2): one warp per row, 8 rows per 256-thread block.
__global__ void __launch_bounds__(256) boruvka_scan() {
    int m = blockIdx.y;
    if (g_done[m]) return;
    const float* __restrict__ dist = (m == 0) ? g_ddist : g_ldist;
    const int* __restrict__ comp = g_comp[m];

    __shared__ __align__(16) int scomp[NPTS];
    for (int t = threadIdx.x; t < NPTS; t += 256) scomp[t] = comp[t];
    __syncthreads();

    int w = threadIdx.x >> 5, lane = threadIdx.x & 31;
    int row = blockIdx.x * 8 + w;
    int mycomp = scomp[row];

    // monotone cache check (uniform across the warp)
    {
        unsigned long long nb = g_nbest[m][row];
        int pj = (int)(nb & 0xFFF);
        if (scomp[pj] != mycomp) return;   // cached best still outgoing -> keep
    }

    const float4* __restrict__ rp = (const float4*)(dist + (size_t)row * NPTS);
    const int4* __restrict__ cp = (const int4*)scomp;

    unsigned bestv = 0xFFFFFFFFu;
    int bestj = 0;
#pragma unroll 8
    for (int k = 0; k < 32; k++) {
        int c4 = k * 32 + lane;
        float4 v = rp[c4];
        int4 cc = cp[c4];
        int col = c4 << 2;
        unsigned b;
        b = __float_as_uint(v.x); if (cc.x != mycomp && b < bestv) { bestv = b; bestj = col; }
        b = __float_as_uint(v.y); if (cc.y != mycomp && b < bestv) { bestv = b; bestj = col + 1; }
        b = __float_as_uint(v.z); if (cc.z != mycomp && b < bestv) { bestv = b; bestj = col + 2; }
        b = __float_as_uint(v.w); if (cc.w != mycomp && b < bestv) { bestv = b; bestj = col + 3; }
    }
    unsigned rv = __reduce_min_sync(0xffffffffu, bestv);
    unsigned rj = __reduce_min_sync(0xffffffffu,
                                    (bestv == rv) ? (unsigned)bestj : 0xFFFFFFFFu);
    if (lane == 0)
        g_nbest[m][row] = ((unsigned long long)rv << 24)
                        | ((unsigned long long)row << 12)
                        | (unsigned long long)rj;
}

// ---- Boruvka merge: per-comp best, hook, pointer-jump, relabel ----
__global__ void __launch_bounds__(1024) boruvka_merge() {
    int m = blockIdx.x;
    if (g_done[m]) return;
    __shared__ __align__(8) unsigned long long table[NPTS];
    __shared__ int scnt;
    int tid = threadIdx.x;
    int* __restrict__ parent = g_parent[m];
    const int* __restrict__ comp = g_comp[m];

    for (int c = tid; c < NPTS; c += 1024) { table[c] = ~0ull; parent[c] = c; }
    if (tid == 0) scnt = 0;
    __syncthreads();

    for (int n = tid; n < NPTS; n += 1024)
        atomicMin(&table[comp[n]], g_nbest[m][n]);
    __syncthreads();

    for (int c = tid; c < NPTS; c += 1024) {
        unsigned long long e = table[c];
        if (e != ~0ull) {
            int i = (int)((e >> 12) & 0xFFF);
            int j = (int)(e & 0xFFF);
            int t = comp[j];
            unsigned long long et = table[t];
            int i2 = (int)((et >> 12) & 0xFFF);
            int j2 = (int)(et & 0xFFF);
            bool mutual = (i2 == j) && (j2 == i);
            if (!mutual || c < t) {
                int pos = atomicAdd(&g_ecnt[m], 1);
                g_edges[m][2 * pos]     = i;
                g_edges[m][2 * pos + 1] = j;
            }
            parent[c] = (mutual && c < t) ? c : t;
        }
    }
    __syncthreads();

    for (int it = 0; it < 12; it++) {
        for (int c = tid; c < NPTS; c += 1024) {
            int p = parent[c];
            parent[c] = parent[p];
        }
        __syncthreads();
    }

    int* mark = (int*)table;
    for (int c = tid; c < NPTS; c += 1024) mark[c] = 0;
    __syncthreads();
    for (int n = tid; n < NPTS; n += 1024) {
        int r = parent[comp[n]];
        g_comp[m][n] = r;
        mark[r] = 1;
    }
    __syncthreads();
    int cnt = 0;
    for (int c = tid; c < NPTS; c += 1024) cnt += mark[c];
#pragma unroll
    for (int off = 16; off; off >>= 1) cnt += __shfl_down_sync(0xffffffffu, cnt, off);
    if ((tid & 31) == 0) atomicAdd(&scnt, cnt);
    __syncthreads();
    if (tid == 0 && scnt == 1) g_done[m] = 1;
}

// ---- gather MST edges from fp32 matrices, compute topo loss ----
__global__ void __launch_bounds__(1024) topo_kernel(const float* __restrict__ lnorm) {
    int tid = threadIdx.x;
    float invmax = 1.0f / __uint_as_float(g_dmax_bits);
    float invln = 1.0f / lnorm[0];
    float sd = 0.f, sl = 0.f;
    for (int e = tid; e < NEDGE; e += 1024) {
        int u = g_edges[0][2 * e], v = g_edges[0][2 * e + 1];
        size_t o = (size_t)u * NPTS + v;
        float t = g_ddist[o] * invmax - g_ldist[o] * invln;
        sd += t * t;
        u = g_edges[1][2 * e]; v = g_edges[1][2 * e + 1];
        o = (size_t)u * NPTS + v;
        t = g_ddist[o] * invmax - g_ldist[o] * invln;
        sl += t * t;
    }
#pragma unroll
    for (int off = 16; off; off >>= 1) {
        sd += __shfl_down_sync(0xffffffffu, sd, off);
        sl += __shfl_down_sync(0xffffffffu, sl, off);
    }
    __shared__ float ssd[32], ssl[32];
    if ((tid & 31) == 0) { ssd[tid >> 5] = sd; ssl[tid >> 5] = sl; }
    __syncthreads();
    if (tid < 32) {
        sd = ssd[tid]; sl = ssl[tid];
#pragma unroll
        for (int off = 16; off; off >>= 1) {
            sd += __shfl_down_sync(0xffffffffu, sd, off);
            sl += __shfl_down_sync(0xffffffffu, sl, off);
        }
        if (tid == 0) g_topo = (sd + sl) * (1.0f / NEDGE);
    }
}

__global__ void final_kernel(float* __restrict__ out) {
    int i = blockIdx.x * blockDim.x + threadIdx.x;
    if (i < NPTS) out[i] = g_ae[i] + 0.5f * g_topo;
}

extern "C" void kernel_launch(void* const* d_in, const int* in_sizes, int n_in,
                              void* d_out, int out_size) {
    const float* y_true      = (const float*)d_in[0];
    const float* latent      = (const float*)d_in[1];
    const float* y_pred      = (const float*)d_in[2];
    const float* latent_norm = (const float*)d_in[3];
    float* out = (float*)d_out;

    static int attr_set = 0;
    if (!attr_set) {
        cudaFuncSetAttribute(gram_kernel,
                             cudaFuncAttributeMaxDynamicSharedMemorySize,
                             GRAM_SMEM);
        attr_set = 1;
    }

    init_kernel<<<16, 256>>>();
    ae_sq_kernel<<<NPTS, 256>>>(y_true, y_pred);
    sq_lat_kernel<<<NPTS, 32>>>(latent);
    gram_kernel<<<dim3(33, 32), 512, GRAM_SMEM>>>(y_true, latent);
    for (int r = 0; r < ROUNDS; r++) {
        boruvka_scan<<<dim3(512, 2), 256>>>();
        boruvka_merge<<<2, 1024>>>();
    }
    topo_kernel<<<1, 1024>>>(latent_norm);
    final_kernel<<<16, 256>>>(out);
}

// round 16
// speedup vs baseline: 1.5266x; 1.0126x over previous
#include <cuda_runtime.h>
#include <cuda_bf16.h>
#include <mma.h>
#include <math_constants.h>

#define NPTS 4096
#define DDATA 1024
#define DLAT 64
#define NEDGE (NPTS - 1)
#define ROUNDS 12
#define SLD 40                  // smem row stride in bf16 elems (80 B)
#define STG (128 * SLD)         // one tile: 5120 bf16 = 10240 B
#define GRAM_SMEM (2 * 4 * STG * 2)  // 2 stages x 4 tiles x 10240 B = 81920 B

using namespace nvcuda;

// ---- scratch (no allocations allowed: device globals) ----
static __device__ float g_ddist[(size_t)NPTS * NPTS];   // raw data distances fp32
static __device__ float g_ldist[(size_t)NPTS * NPTS];   // raw latent distances fp32
static __device__ float g_sqd[NPTS];
static __device__ float g_sql[NPTS];
static __device__ float g_ae[NPTS];
static __device__ int   g_edges[2][NEDGE * 2];
static __device__ int   g_ecnt[2];
static __device__ int   g_done[2];
static __device__ int   g_comp[2][NPTS];
static __device__ int   g_parent[2][NPTS];
static __device__ unsigned long long g_nbest[2][NPTS];
static __device__ unsigned g_dmax_bits;
static __device__ float g_topo;

__global__ void init_kernel() {
    int i = blockIdx.x * blockDim.x + threadIdx.x;
    if (i < NPTS) {
        g_comp[0][i] = i; g_comp[1][i] = i;
        // max sentinel: gram epilogue atomicMin's the round-0 best edges in
        g_nbest[0][i] = ~0ull;
        g_nbest[1][i] = ~0ull;
    }
    if (i == 0) {
        g_dmax_bits = 0u;
        g_ecnt[0] = 0; g_ecnt[1] = 0;
        g_done[0] = 0; g_done[1] = 0;
    }
}

// ---- AE loss + squared norms of y_true (one block per row) ----
__global__ void __launch_bounds__(256) ae_sq_kernel(
    const float* __restrict__ yt, const float* __restrict__ yp) {
    int row = blockIdx.x, tid = threadIdx.x;
    float4 a = ((const float4*)(yt + (size_t)row * DDATA))[tid];
    float4 b = ((const float4*)(yp + (size_t)row * DDATA))[tid];
    float dx = a.x - b.x, dy = a.y - b.y, dz = a.z - b.z, dw = a.w - b.w;
    float ae = dx * dx + dy * dy + dz * dz + dw * dw;
    float sq = a.x * a.x + a.y * a.y + a.z * a.z + a.w * a.w;
#pragma unroll
    for (int off = 16; off; off >>= 1) {
        ae += __shfl_down_sync(0xffffffffu, ae, off);
        sq += __shfl_down_sync(0xffffffffu, sq, off);
    }
    __shared__ float sae[8], ssq[8];
    if ((tid & 31) == 0) { sae[tid >> 5] = ae; ssq[tid >> 5] = sq; }
    __syncthreads();
    if (tid < 8) {
        ae = sae[tid]; sq = ssq[tid];
#pragma unroll
        for (int off = 4; off; off >>= 1) {
            ae += __shfl_down_sync(0xffu, ae, off);
            sq += __shfl_down_sync(0xffu, sq, off);
        }
        if (tid == 0) { g_ae[row] = ae * (1.0f / DDATA); g_sqd[row] = sq; }
    }
}

// ---- squared norms of latent rows (one warp per row) ----
__global__ void __launch_bounds__(32) sq_lat_kernel(const float* __restrict__ lat) {
    int row = blockIdx.x, tid = threadIdx.x;
    float2 v = ((const float2*)(lat + (size_t)row * DLAT))[tid];
    float s = v.x * v.x + v.y * v.y;
#pragma unroll
    for (int off = 16; off; off >>= 1) s += __shfl_down_sync(0xffffffffu, s, off);
    if (tid == 0) g_sql[row] = s;
}

// ---- fused tensor-core gram -> distance matrices + Boruvka round-0 bests ----
// grid (33, 32): bx<32 & by<=bx -> data tile (by,bx); bx<32 & by>bx -> latent
// tile (bx,by); bx==32 -> latent diagonal tile (by,by).
// 512 threads, 16 warps (32x32 warp tile), 128x128 block tile, wmma bf16
// m16n16k16, bf16-split 3-pass (hi*hi + hi*lo + lo*hi, proven rel_err 8.9e-9),
// double-buffered smem + register prefetch.
// R16: epilogue additionally reduces per-row/per-col min outgoing edges
// (round 0: every node is its own component) into g_nbest via atomicMin.
__global__ void __launch_bounds__(512) gram_kernel(
    const float* __restrict__ Yd, const float* __restrict__ Yl) {
    int bx = blockIdx.x, by = blockIdx.y;
    int bi, bj, which;
    if (bx < 32) {
        if (by <= bx) { which = 0; bi = by; bj = bx; }
        else          { which = 1; bi = bx; bj = by; }
    } else            { which = 1; bi = by; bj = by; }
    const float* __restrict__ X  = which ? Yl : Yd;
    const int K = which ? DLAT : DDATA;
    const float* __restrict__ sq = which ? g_sql : g_sqd;
    float* __restrict__ D = which ? g_ldist : g_ddist;

    extern __shared__ __align__(16) __nv_bfloat16 smbuf[];   // 2 stages x 4 tiles

    int tid = threadIdx.x, lane = tid & 31, wid = tid >> 5;   // wid 0..15
    int wm = wid & 3;        // m offset = wm*32
    int wn = wid >> 2;       // n offset = wn*32

    wmma::fragment<wmma::accumulator, 16, 16, 16, float> acc[2][2];
#pragma unroll
    for (int mi = 0; mi < 2; mi++)
#pragma unroll
        for (int ni = 0; ni < 2; ni++) wmma::fill_fragment(acc[mi][ni], 0.0f);

    int lr = tid >> 2;              // 0..127
    int lk = (tid & 3) << 3;        // 0,8,16,24
    const float* Ap = X + (size_t)(bi * 128 + lr) * K;
    const float* Bp = X + (size_t)(bj * 128 + lr) * K;

    const int NC = K / 32;
    uint4 pa[2], pb[2];
#pragma unroll
    for (int i = 0; i < 2; i++) {
        pa[i] = *(const uint4*)(Ap + lk + i * 4);
        pb[i] = *(const uint4*)(Bp + lk + i * 4);
    }

#pragma unroll 1
    for (int c = 0; c < NC; c++) {
        __nv_bfloat16* Ahi = smbuf + (c & 1) * 4 * STG;
        __nv_bfloat16* Alo = Ahi + STG;
        __nv_bfloat16* Bhi = Ahi + 2 * STG;
        __nv_bfloat16* Blo = Ahi + 3 * STG;

#pragma unroll
        for (int i = 0; i < 2; i++) {
            int ke = lk + i * 4;
            float4 a = *(const float4*)&pa[i];
            float4 b = *(const float4*)&pb[i];
            __nv_bfloat162 ah01(__float2bfloat16(a.x), __float2bfloat16(a.y));
            __nv_bfloat162 ah23(__float2bfloat16(a.z), __float2bfloat16(a.w));
            __nv_bfloat162 al01(
                __float2bfloat16(a.x - __bfloat162float(ah01.x)),
                __float2bfloat16(a.y - __bfloat162float(ah01.y)));
            __nv_bfloat162 al23(
                __float2bfloat16(a.z - __bfloat162float(ah23.x)),
                __float2bfloat16(a.w - __bfloat162float(ah23.y)));
            __nv_bfloat162 bh01(__float2bfloat16(b.x), __float2bfloat16(b.y));
            __nv_bfloat162 bh23(__float2bfloat16(b.z), __float2bfloat16(b.w));
            __nv_bfloat162 bl01(
                __float2bfloat16(b.x - __bfloat162float(bh01.x)),
                __float2bfloat16(b.y - __bfloat162float(bh01.y)));
            __nv_bfloat162 bl23(
                __float2bfloat16(b.z - __bfloat162float(bh23.x)),
                __float2bfloat16(b.w - __bfloat162float(bh23.y)));
            unsigned long long vah, val, vbh, vbl;
            ((__nv_bfloat162*)&vah)[0] = ah01; ((__nv_bfloat162*)&vah)[1] = ah23;
            ((__nv_bfloat162*)&val)[0] = al01; ((__nv_bfloat162*)&val)[1] = al23;
            ((__nv_bfloat162*)&vbh)[0] = bh01; ((__nv_bfloat162*)&vbh)[1] = bh23;
            ((__nv_bfloat162*)&vbl)[0] = bl01; ((__nv_bfloat162*)&vbl)[1] = bl23;
            *(unsigned long long*)(Ahi + lr * SLD + ke) = vah;
            *(unsigned long long*)(Alo + lr * SLD + ke) = val;
            *(unsigned long long*)(Bhi + lr * SLD + ke) = vbh;
            *(unsigned long long*)(Blo + lr * SLD + ke) = vbl;
        }
        __syncthreads();

        if (c + 1 < NC) {
            int k1 = (c + 1) * 32;
#pragma unroll
            for (int i = 0; i < 2; i++) {
                pa[i] = *(const uint4*)(Ap + k1 + lk + i * 4);
                pb[i] = *(const uint4*)(Bp + k1 + lk + i * 4);
            }
        }

#pragma unroll
        for (int kk = 0; kk < 32; kk += 16) {
            wmma::fragment<wmma::matrix_a, 16, 16, 16, __nv_bfloat16, wmma::row_major> ah[2], al[2];
#pragma unroll
            for (int mi = 0; mi < 2; mi++) {
                wmma::load_matrix_sync(ah[mi], Ahi + (wm * 32 + mi * 16) * SLD + kk, SLD);
                wmma::load_matrix_sync(al[mi], Alo + (wm * 32 + mi * 16) * SLD + kk, SLD);
            }
#pragma unroll
            for (int ni = 0; ni < 2; ni++) {
                wmma::fragment<wmma::matrix_b, 16, 16, 16, __nv_bfloat16, wmma::col_major> bh, bl;
                wmma::load_matrix_sync(bh, Bhi + (wn * 32 + ni * 16) * SLD + kk, SLD);
                wmma::load_matrix_sync(bl, Blo + (wn * 32 + ni * 16) * SLD + kk, SLD);
#pragma unroll
                for (int mi = 0; mi < 2; mi++) {
                    wmma::mma_sync(acc[mi][ni], ah[mi], bh, acc[mi][ni]);
                    wmma::mma_sync(acc[mi][ni], ah[mi], bl, acc[mi][ni]);
                    wmma::mma_sync(acc[mi][ni], al[mi], bh, acc[mi][ni]);
                }
            }
        }
    }
    __syncthreads();   // before reusing smbuf as epilogue staging

    // epilogue: d = sqrt(max(sq_i+sq_j-2g, 0)), fp32 out, + round-0 min edges
    float* sc = (float*)smbuf;                              // 16 warps x 256 floats
    unsigned long long* rowbest =
        (unsigned long long*)((char*)smbuf + 16384);        // [128]
    unsigned long long* colbest = rowbest + 128;            // [128]
    if (tid < 256) rowbest[tid] = ~0ull;                    // rowbest+colbest
    __syncthreads();

    float lmax = 0.f;
#pragma unroll
    for (int mi = 0; mi < 2; mi++) {
#pragma unroll
        for (int ni = 0; ni < 2; ni++) {
            wmma::store_matrix_sync(sc + wid * 256, acc[mi][ni], 16, wmma::mem_row_major);
            __syncwarp();
            int m0 = bi * 128 + wm * 32 + mi * 16;
            int n0 = bj * 128 + wn * 32 + ni * 16;
            int r = lane >> 1;
            int c0 = (lane & 1) << 3;
            int gi = m0 + r;
            float sqa = sq[gi];
            unsigned bvr = 0xFFFFFFFFu; int bjr = 0;
#pragma unroll
            for (int t = 0; t < 8; t++) {
                int c = c0 + t;
                float g = sc[wid * 256 + r * 16 + c];
                int gj = n0 + c;
                float d2 = sqa + sq[gj] - 2.0f * g;
                float d = (d2 > 0.f) ? sqrtf(d2) : 0.f;
                D[(size_t)gi * NPTS + gj] = d;
                if (bi != bj) D[(size_t)gj * NPTS + gi] = d;
                lmax = fmaxf(lmax, d);
                if (gi != gj) {
                    unsigned dv = __float_as_uint(d);
                    if (dv < bvr) { bvr = dv; bjr = gj; }
                    if (bi != bj)
                        atomicMin(&colbest[wn * 32 + ni * 16 + c],
                                  ((unsigned long long)dv << 24) |
                                  ((unsigned long long)gj << 12) |
                                  (unsigned long long)gi);
                }
            }
            if (bvr != 0xFFFFFFFFu)
                atomicMin(&rowbest[wm * 32 + mi * 16 + r],
                          ((unsigned long long)bvr << 24) |
                          ((unsigned long long)gi << 12) |
                          (unsigned long long)bjr);
            __syncwarp();
        }
    }
    __syncthreads();

    // one global atomicMin per row/col of this tile
    if (tid < 128) {
        unsigned long long v = rowbest[tid];
        if (v != ~0ull) atomicMin(&g_nbest[which][bi * 128 + tid], v);
    } else if (tid < 256) {
        unsigned long long v = colbest[tid - 128];
        if (v != ~0ull) atomicMin(&g_nbest[which][bj * 128 + (tid - 128)], v);
    }

    if (which == 0) {
#pragma unroll
        for (int off = 16; off; off >>= 1)
            lmax = fmaxf(lmax, __shfl_down_sync(0xffffffffu, lmax, off));
        __shared__ float smax[16];
        if (lane == 0) smax[wid] = lmax;
        __syncthreads();
        if (tid == 0) {
            float mx = smax[0];
#pragma unroll
            for (int w = 1; w < 16; w++) mx = fmaxf(mx, smax[w]);
            atomicMax(&g_dmax_bits, __float_as_uint(mx));
        }
    }
}

// ---- Boruvka scan over fp32 matrix with monotone cache + early exit ----
// grid (512, 2): one warp per row, 8 rows per 256-thread block.
// Cache rule: if the row's cached best edge target is still outside the row's
// component, the cached edge is still the row's min outgoing edge -> skip.
// Block-level early exit: if all 8 rows are cached, return without staging.
__global__ void __launch_bounds__(256) boruvka_scan() {
    int m = blockIdx.y;
    if (g_done[m]) return;
    const float* __restrict__ dist = (m == 0) ? g_ddist : g_ldist;
    const int* __restrict__ comp = g_comp[m];

    __shared__ __align__(16) int scomp[NPTS];
    __shared__ int nscan;

    int tid = threadIdx.x;
    int w = tid >> 5, lane = tid & 31;
    int row = blockIdx.x * 8 + w;

    if (tid == 0) nscan = 0;
    __syncthreads();

    int cached = 1;
    if (lane == 0) {
        unsigned long long nb = g_nbest[m][row];
        int pj = (int)(nb & 0xFFF);
        cached = (comp[pj] != comp[row]);
        if (!cached) atomicAdd(&nscan, 1);
    }
    __syncthreads();
    if (nscan == 0) return;
    cached = __shfl_sync(0xffffffffu, cached, 0);

    // stage scomp (all threads participate, cached warps exit after)
    for (int t = tid; t < NPTS; t += 256) scomp[t] = comp[t];
    __syncthreads();
    if (cached) return;

    int mycomp = scomp[row];
    const float4* __restrict__ rp = (const float4*)(dist + (size_t)row * NPTS);
    const int4* __restrict__ cp = (const int4*)scomp;

    unsigned bestv = 0xFFFFFFFFu;
    int bestj = 0;
#pragma unroll 8
    for (int k = 0; k < 32; k++) {
        int c4 = k * 32 + lane;
        float4 v = rp[c4];
        int4 cc = cp[c4];
        int col = c4 << 2;
        unsigned b;
        b = __float_as_uint(v.x); if (cc.x != mycomp && b < bestv) { bestv = b; bestj = col; }
        b = __float_as_uint(v.y); if (cc.y != mycomp && b < bestv) { bestv = b; bestj = col + 1; }
        b = __float_as_uint(v.z); if (cc.z != mycomp && b < bestv) { bestv = b; bestj = col + 2; }
        b = __float_as_uint(v.w); if (cc.w != mycomp && b < bestv) { bestv = b; bestj = col + 3; }
    }
    unsigned rv = __reduce_min_sync(0xffffffffu, bestv);
    unsigned rj = __reduce_min_sync(0xffffffffu,
                                    (bestv == rv) ? (unsigned)bestj : 0xFFFFFFFFu);
    if (lane == 0)
        g_nbest[m][row] = ((unsigned long long)rv << 24)
                        | ((unsigned long long)row << 12)
                        | (unsigned long long)rj;
}

// ---- Boruvka merge: per-comp best, hook, pointer-jump, relabel ----
__global__ void __launch_bounds__(1024) boruvka_merge() {
    int m = blockIdx.x;
    if (g_done[m]) return;
    __shared__ __align__(8) unsigned long long table[NPTS];
    __shared__ int scnt;
    int tid = threadIdx.x;
    int* __restrict__ parent = g_parent[m];
    const int* __restrict__ comp = g_comp[m];

    for (int c = tid; c < NPTS; c += 1024) { table[c] = ~0ull; parent[c] = c; }
    if (tid == 0) scnt = 0;
    __syncthreads();

    for (int n = tid; n < NPTS; n += 1024)
        atomicMin(&table[comp[n]], g_nbest[m][n]);
    __syncthreads();

    for (int c = tid; c < NPTS; c += 1024) {
        unsigned long long e = table[c];
        if (e != ~0ull) {
            int i = (int)((e >> 12) & 0xFFF);
            int j = (int)(e & 0xFFF);
            int t = comp[j];
            unsigned long long et = table[t];
            int i2 = (int)((et >> 12) & 0xFFF);
            int j2 = (int)(et & 0xFFF);
            bool mutual = (i2 == j) && (j2 == i);
            if (!mutual || c < t) {
                int pos = atomicAdd(&g_ecnt[m], 1);
                g_edges[m][2 * pos]     = i;
                g_edges[m][2 * pos + 1] = j;
            }
            parent[c] = (mutual && c < t) ? c : t;
        }
    }
    __syncthreads();

    for (int it = 0; it < 12; it++) {
        for (int c = tid; c < NPTS; c += 1024) {
            int p = parent[c];
            parent[c] = parent[p];
        }
        __syncthreads();
    }

    int* mark = (int*)table;
    for (int c = tid; c < NPTS; c += 1024) mark[c] = 0;
    __syncthreads();
    for (int n = tid; n < NPTS; n += 1024) {
        int r = parent[comp[n]];
        g_comp[m][n] = r;
        mark[r] = 1;
    }
    __syncthreads();
    int cnt = 0;
    for (int c = tid; c < NPTS; c += 1024) cnt += mark[c];
#pragma unroll
    for (int off = 16; off; off >>= 1) cnt += __shfl_down_sync(0xffffffffu, cnt, off);
    if ((tid & 31) == 0) atomicAdd(&scnt, cnt);
    __syncthreads();
    if (tid == 0 && scnt == 1) g_done[m] = 1;
}

// ---- gather MST edges from fp32 matrices, compute topo loss ----
__global__ void __launch_bounds__(1024) topo_kernel(const float* __restrict__ lnorm) {
    int tid = threadIdx.x;
    float invmax = 1.0f / __uint_as_float(g_dmax_bits);
    float invln = 1.0f / lnorm[0];
    float sd = 0.f, sl = 0.f;
    for (int e = tid; e < NEDGE; e += 1024) {
        int u = g_edges[0][2 * e], v = g_edges[0][2 * e + 1];
        size_t o = (size_t)u * NPTS + v;
        float t = g_ddist[o] * invmax - g_ldist[o] * invln;
        sd += t * t;
        u = g_edges[1][2 * e]; v = g_edges[1][2 * e + 1];
        o = (size_t)u * NPTS + v;
        t = g_ddist[o] * invmax - g_ldist[o] * invln;
        sl += t * t;
    }
#pragma unroll
    for (int off = 16; off; off >>= 1) {
        sd += __shfl_down_sync(0xffffffffu, sd, off);
        sl += __shfl_down_sync(0xffffffffu, sl, off);
    }
    __shared__ float ssd[32], ssl[32];
    if ((tid & 31) == 0) { ssd[tid >> 5] = sd; ssl[tid >> 5] = sl; }
    __syncthreads();
    if (tid < 32) {
        sd = ssd[tid]; sl = ssl[tid];
#pragma unroll
        for (int off = 16; off; off >>= 1) {
            sd += __shfl_down_sync(0xffffffffu, sd, off);
            sl += __shfl_down_sync(0xffffffffu, sl, off);
        }
        if (tid == 0) g_topo = (sd + sl) * (1.0f / NEDGE);
    }
}

__global__ void final_kernel(float* __restrict__ out) {
    int i = blockIdx.x * blockDim.x + threadIdx.x;
    if (i < NPTS) out[i] = g_ae[i] + 0.5f * g_topo;
}

extern "C" void kernel_launch(void* const* d_in, const int* in_sizes, int n_in,
                              void* d_out, int out_size) {
    const float* y_true      = (const float*)d_in[0];
    const float* latent      = (const float*)d_in[1];
    const float* y_pred      = (const float*)d_in[2];
    const float* latent_norm = (const float*)d_in[3];
    float* out = (float*)d_out;

    static int attr_set = 0;
    if (!attr_set) {
        cudaFuncSetAttribute(gram_kernel,
                             cudaFuncAttributeMaxDynamicSharedMemorySize,
                             GRAM_SMEM);
        attr_set = 1;
    }

    init_kernel<<<16, 256>>>();
    ae_sq_kernel<<<NPTS, 256>>>(y_true, y_pred);
    sq_lat_kernel<<<NPTS, 32>>>(latent);
    gram_kernel<<<dim3(33, 32), 512, GRAM_SMEM>>>(y_true, latent);
    for (int r = 0; r < ROUNDS; r++) {
        boruvka_scan<<<dim3(512, 2), 256>>>();
        boruvka_merge<<<2, 1024>>>();
    }
    topo_kernel<<<1, 1024>>>(latent_norm);
    final_kernel<<<16, 256>>>(out);
}